// round 8
// baseline (speedup 1.0000x reference)
#include <cuda_runtime.h>
#include <math.h>

#define BATCH   64
#define NLIST   512
#define THREADS 512
#define NBLK1   (BATCH * 4)    // rank_partial: 4 j-quarters per row
#define NBLK2   (BATCH * 4)    // pair_main: 4 offset-quarters per row
#define OCHUNK  64

#define LOG_EPS (-23.025850929940457f)
#define LN2F    0.6931471805599453f

// 1/log1p(k) for k=0..52 (k=0 unused)
__constant__ float C_IL[53] = {
    0.0f,        1.44269504f, 0.91023923f, 0.72134752f, 0.62133493f,
    0.55811063f, 0.51389834f, 0.48089835f, 0.45511961f, 0.43429448f,
    0.41703239f, 0.40242960f, 0.38987124f, 0.37892269f, 0.36926938f,
    0.36067376f, 0.35295525f, 0.34597526f, 0.33962297f, 0.33380821f,
    0.32845724f, 0.32351538f, 0.31892891f, 0.31465802f, 0.31066747f,
    0.30692762f, 0.30341308f, 0.30010212f, 0.29697521f, 0.29401538f,
    0.29120814f, 0.28853901f, 0.28599983f, 0.28357871f, 0.28126653f,
    0.27905531f, 0.27693789f, 0.27490773f, 0.27295812f, 0.27108450f,
    0.26928330f, 0.26754748f, 0.26587369f, 0.26425870f, 0.26269878f,
    0.26119069f, 0.25973142f, 0.25831873f, 0.25694924f, 0.25562222f,
    0.25433417f, 0.25308478f, 0.25187249f
};

// partial rank counts: [(b*512 + i)*4 + quarter], each <= 128, byte-wide.
// Every byte overwritten each launch (replay-safe), distinct bytes (race-free).
__device__ unsigned char g_pc[BATCH * NLIST * 4];
__device__ float         g_partial[NBLK2];
__device__ unsigned int  g_count = 0;

// ---------------- kernel 1: partial rank counts --------------------------
__global__ __launch_bounds__(THREADS)
void rank_partial(const float* __restrict__ logits,
                  const float* __restrict__ labels) {
    __shared__ float s_lg[128];
    const int tid = threadIdx.x;
    const int b   = blockIdx.x >> 2;
    const int q   = blockIdx.x & 3;

    if (tid < 128) {
        const int   j  = (q << 7) + tid;
        const float lr = labels[b * NLIST + j];
        const float gr = logits[b * NLIST + j];
        s_lg[tid] = (lr > -1000.0f) ? gr : LOG_EPS;
    }
    __syncthreads();

    const float lr = labels[b * NLIST + tid];
    const float gr = logits[b * NLIST + tid];
    const float g  = (lr > -1000.0f) ? gr : LOG_EPS;

    int c0 = 0, c1 = 0, c2 = 0, c3 = 0;
    const float4* p4 = (const float4*)s_lg;
    #pragma unroll 8
    for (int k = 0; k < 32; ++k) {
        float4 v = p4[k];                // uniform addr -> broadcast
        c0 += (v.x > g);
        c1 += (v.y > g);
        c2 += (v.z > g);
        c3 += (v.w > g);
    }
    g_pc[(b * NLIST + tid) * 4 + q] = (unsigned char)(c0 + c1 + c2 + c3);
}

// ---------------- kernel 2: pairwise loss --------------------------------
__global__ __launch_bounds__(THREADS, 2)
void pair_main(const float* __restrict__ logits,
               const float* __restrict__ labels,
               float* __restrict__ out) {
    __shared__ float4        sA[NLIST + 256];   // {Gj, Ej, hj, labj(NaN invalid)} + mirror
    __shared__ unsigned char sC[NLIST + 256];   // capped rank + mirror
    __shared__ float         s_W[52 * 52];      // 2D weight LUT w(ci,cj)
    __shared__ float         s_red[16];
    __shared__ bool          s_last;

    const int tid  = threadIdx.x;
    const int lane = tid & 31;
    const int b    = blockIdx.x >> 2;
    const int oq   = blockIdx.x & 3;

    // --- W LUT from constant literals ---
    for (int idx = tid; idx < 52 * 52; idx += THREADS) {
        const int ci = idx / 52;
        const int cj = idx - ci * 52;
        const int rd = abs(ci - cj);
        const float rel = rd ? 0.75f * fabsf(C_IL[rd] - C_IL[rd + 1]) : 0.0f;
        const float di  = (ci >= 1 && ci <= 50) ? C_IL[ci] : 0.0f;
        const float dj  = (cj >= 1 && cj <= 50) ? C_IL[cj] : 0.0f;
        s_W[idx] = rel + 0.25f * fabsf(di - dj);
    }

    // --- per-element: inputs + rank via dp4a over the 4 byte-partials ---
    const float gr = logits[b * NLIST + tid];
    const float lr = labels[b * NLIST + tid];
    const bool  valid = lr > -1000.0f;
    const float lab = valid ? lr : 0.0f;
    const float g   = valid ? gr : LOG_EPS;

    const unsigned pc4  = *(const unsigned*)&g_pc[(b * NLIST + tid) * 4];
    const int      rank = (int)__dp4a(pc4, 0x01010101u, 1u);   // 1 + sum of bytes
    const int      capped = min(rank, 51);

    const float Gi   = __expf(0.5f * g);     // exp(logit/2)
    const float Ei   = __expf(0.5f * lab);   // exp(label/2)
    const float hi   = 0.5f * g;
    const float nhi  = -hi;
    const float qnan = __int_as_float(0x7fffffff);
    const float labi = valid ? lab : qnan;   // NaN sentinel -> pair inactive

    const float4 Av = make_float4(Gi, Ei, hi, labi);
    sA[tid] = Av;
    sC[tid] = (unsigned char)capped;
    if (tid < 256) { sA[NLIST + tid] = Av; sC[NLIST + tid] = (unsigned char)capped; }
    __syncthreads();

    // --- per-row IDCG (thread 0; position-based, first 50 positions) ---
    float idcg = 0.0f;
    if (tid == 0) {
        float s = 0.0f;
        #pragma unroll
        for (int p = 1; p <= 50; ++p)
            if (sA[p - 1].w < 1e30f) s += C_IL[p];   // NaN -> false
        idcg = (s > 0.0f) ? (1.0f / s) : 0.0f;
    }

    // --- pair loop: orientation-free identity (exact both directions):
    //     bce = ln2*lg2(Gi+Gj) - hi + dh*Ej/(Ei+Ej),  dh = hi-hj
    //     w = W[ci][cj];  mask |labi-labj|>0 (NaN-safe).
    //     Offsets 1..256 quartered; offset 256 double-covered -> gate tid<256. ---
    const float4*        pA   = sA + tid + 1 + (oq << 6);
    const unsigned char* pC   = sC + tid + 1 + (oq << 6);
    const float*         Wrow = s_W + capped * 52;

    auto body = [&](const float4 A, const int cj) -> float {
        const float t2  = __fdividef(A.y, Ei + A.y);
        const float lg  = __log2f(Gi + A.x);
        const float dh  = hi - A.z;
        const float bce = fmaf(dh, t2, fmaf(lg, LN2F, nhi));
        const float dl  = labi - A.w;                  // NaN if either invalid
        const float wv  = Wrow[cj];
        const float w   = (fabsf(dl) > 0.0f) ? wv : 0.0f;
        return bce * w;
    };

    float acc0 = 0.0f, acc1 = 0.0f, acc2 = 0.0f, acc3 = 0.0f;
    int oo = 0;
    for (; oo + 4 <= OCHUNK - 4; oo += 4) {            // offsets 0..59 in 4-wide batches
        const float4 A0 = pA[oo],     A1 = pA[oo + 1];
        const float4 A2 = pA[oo + 2], A3 = pA[oo + 3];
        const int    j0 = pC[oo],     j1 = pC[oo + 1];
        const int    j2 = pC[oo + 2], j3 = pC[oo + 3];
        acc0 += body(A0, j0);
        acc1 += body(A1, j1);
        acc2 += body(A2, j2);
        acc3 += body(A3, j3);
    }
    for (; oo < OCHUNK - 1; ++oo)                      // offsets 60..62
        acc0 += body(pA[oo], pC[oo]);
    {   // last offset of quarter; oq==3 hits offset 256 (double-covered) -> gate
        const bool gate = (oq != 3) | (tid < 256);
        const float v = body(pA[OCHUNK - 1], pC[OCHUNK - 1]);
        acc1 += gate ? v : 0.0f;
    }
    float acc = (acc0 + acc1) + (acc2 + acc3);

    // --- deterministic block reduce + fused final reduce ---
    #pragma unroll
    for (int o = 16; o; o >>= 1) acc += __shfl_down_sync(0xffffffffu, acc, o);
    if (lane == 0) s_red[tid >> 5] = acc;
    __syncthreads();
    if (tid < 16) {
        float v = s_red[tid];
        #pragma unroll
        for (int o = 8; o; o >>= 1) v += __shfl_down_sync(0xffffu, v, o);
        if (tid == 0) {
            g_partial[blockIdx.x] = v * idcg * (1.0f / (float)BATCH);
            __threadfence();
            unsigned int old = atomicInc(&g_count, NBLK2 - 1);  // wraps -> replay-safe
            s_last = (old == NBLK2 - 1);
        }
    }
    __syncthreads();

    if (s_last) {
        __threadfence();
        if (tid < NBLK2) {
            float v = ((volatile float*)g_partial)[tid];
            #pragma unroll
            for (int o = 16; o; o >>= 1) v += __shfl_down_sync(0xffffffffu, v, o);
            if (lane == 0) s_red[tid >> 5] = v;
        }
        __syncthreads();
        if (tid == 0) {
            float tot = 0.0f;
            #pragma unroll
            for (int w2 = 0; w2 < NBLK2 / 32; ++w2) tot += s_red[w2];
            out[0] = tot;
        }
    }
}

extern "C" void kernel_launch(void* const* d_in, const int* in_sizes, int n_in,
                              void* d_out, int out_size) {
    const float* logits = (const float*)d_in[0];
    const float* labels = (const float*)d_in[1];
    float* out = (float*)d_out;
    (void)in_sizes; (void)n_in; (void)out_size;

    rank_partial<<<NBLK1, THREADS>>>(logits, labels);
    pair_main<<<NBLK2, THREADS>>>(logits, labels, out);
}

// round 9
// speedup vs baseline: 1.5431x; 1.5431x over previous
#include <cuda_runtime.h>
#include <math.h>

#define BATCH   64
#define NLIST   512
#define THREADS 512
#define NBLK    128            // 2 blocks per row = 1 cluster per row

#define LOG_EPS (-23.025850929940457f)
#define LN2F    0.6931471805599453f

// 1/log1p(k) for k=0..52 (k=0 unused)
__constant__ float C_IL[53] = {
    0.0f,        1.44269504f, 0.91023923f, 0.72134752f, 0.62133493f,
    0.55811063f, 0.51389834f, 0.48089835f, 0.45511961f, 0.43429448f,
    0.41703239f, 0.40242960f, 0.38987124f, 0.37892269f, 0.36926938f,
    0.36067376f, 0.35295525f, 0.34597526f, 0.33962297f, 0.33380821f,
    0.32845724f, 0.32351538f, 0.31892891f, 0.31465802f, 0.31066747f,
    0.30692762f, 0.30341308f, 0.30010212f, 0.29697521f, 0.29401538f,
    0.29120814f, 0.28853901f, 0.28599983f, 0.28357871f, 0.28126653f,
    0.27905531f, 0.27693789f, 0.27490773f, 0.27295812f, 0.27108450f,
    0.26928330f, 0.26754748f, 0.26587369f, 0.26425870f, 0.26269878f,
    0.26119069f, 0.25973142f, 0.25831873f, 0.25694924f, 0.25562222f,
    0.25433417f, 0.25308478f, 0.25187249f
};

__device__ float        g_partial[NBLK];
__device__ unsigned int g_count = 0;

__global__ __launch_bounds__(THREADS, 1) __cluster_dims__(2, 1, 1)
void rank_loss_main(const float* __restrict__ logits,
                    const float* __restrict__ labels,
                    float* __restrict__ out) {
    __shared__ float  s_sl[NLIST];        // masked logits (rank phase)
    __shared__ float4 sA[NLIST + 256];    // {Gj, Ej, hj, labj(NaN invalid)} + mirror
    __shared__ float  sBp[NLIST + 256];   // qd with capped in low 8 mantissa bits + mirror
    __shared__ int    s_cnt[THREADS];     // partial rank counts
    __shared__ __align__(4) unsigned char sC[NLIST];  // capped ranks (cluster-shared)
    __shared__ float  s_rel[103 * 32];    // symmetric replicated: [(d)*32+lane], d=ci-cj+51
    __shared__ float  s_red[16];
    __shared__ bool   s_last;

    const int tid  = threadIdx.x;
    const int lane = tid & 31;
    const int b    = blockIdx.x >> 1;
    const int h    = blockIdx.x & 1;      // == cluster ctarank (cluster dims (2,1,1))

    // --- symmetric replicated rel LUT from constant literals ---
    for (int idx = tid; idx < 103 * 32; idx += THREADS) {
        const int d = idx >> 5;
        const int k = abs(d - 51);
        s_rel[idx] = k ? 0.75f * fabsf(C_IL[k] - C_IL[k + 1]) : 0.0f;
    }

    // --- per-element load / masking / sA fill ---
    const float gr    = logits[b * NLIST + tid];
    const float lr    = labels[b * NLIST + tid];
    const bool  valid = lr > -1000.0f;
    const float lab   = valid ? lr : 0.0f;
    const float g     = valid ? gr : LOG_EPS;
    s_sl[tid] = g;

    const float Gi   = __expf(0.5f * g);    // exp(logit/2)
    const float Ei   = __expf(0.5f * lab);  // exp(label/2)
    const float hi   = 0.5f * g;
    const float nhi  = -hi;
    const float qnan = __int_as_float(0x7fffffff);
    const float labi = valid ? lab : qnan;  // NaN sentinel -> pair inactive

    const float4 Av = make_float4(Gi, Ei, hi, labi);
    sA[tid] = Av;
    if (tid < 256) sA[NLIST + tid] = Av;
    __syncthreads();

    // --- split rank scan: this CTA ranks its 256 elements, 2 threads each ---
    // element el = h*256 + (tid&255); this thread scans j-half (tid>>8).
    const int   el = (h << 8) + (tid & 255);
    const int   jh = tid >> 8;
    const float ge = s_sl[el];
    int c0 = 0, c1 = 0, c2 = 0, c3 = 0;
    const float4* p4 = (const float4*)(s_sl + (jh << 8));
    #pragma unroll 8
    for (int k = 0; k < 64; ++k) {
        float4 v = p4[k];                  // uniform addr across warp -> broadcast
        c0 += (v.x > ge);
        c1 += (v.y > ge);
        c2 += (v.z > ge);
        c3 += (v.w > ge);
    }
    s_cnt[tid] = c0 + c1 + c2 + c3;
    __syncthreads();

    if (tid < 256) {
        const int cnt = s_cnt[tid] + s_cnt[tid + 256];
        // ties only among the invalid cluster (all at LOG_EPS): capped=51 either
        // way and such elements appear only in masked pairs -> plain '>' exact
        sC[el] = (unsigned char)min(cnt + 1, 51);
    }
    __syncthreads();

    // --- DSMEM exchange: push our 256 capped bytes into peer CTA's sC ---
    if (tid < 64) {
        const int off = (h << 8) + (tid << 2);
        const unsigned w32   = *(const unsigned*)&sC[off];
        const unsigned laddr = (unsigned)__cvta_generic_to_shared(&sC[off]);
        unsigned paddr;
        asm("mapa.shared::cluster.u32 %0, %1, %2;"
            : "=r"(paddr) : "r"(laddr), "r"(h ^ 1));
        asm volatile("st.shared::cluster.u32 [%0], %1;"
                     :: "r"(paddr), "r"(w32) : "memory");
    }
    // cluster barrier: orders DSMEM stores, doubles as block barrier
    asm volatile("barrier.cluster.arrive.aligned;" ::: "memory");
    asm volatile("barrier.cluster.wait.aligned;" ::: "memory");

    // --- per-element qd + pack (capped in low 8 mantissa bits of qd) ---
    const int   capped = sC[tid];
    const float qdi    = (capped <= 50) ? 0.25f * C_IL[capped] : 0.0f;
    const unsigned qbits = (__float_as_uint(qdi) & ~0xFFu) | (unsigned)capped;
    sBp[tid] = __uint_as_float(qbits);
    if (tid < 256) sBp[NLIST + tid] = __uint_as_float(qbits);
    __syncthreads();

    // --- per-row IDCG (thread 0; first 50 positions, validity via NaN sentinel) ---
    float idcg = 0.0f;
    if (tid == 0) {
        float s = 0.0f;
        #pragma unroll
        for (int p = 1; p <= 50; ++p)
            if (sA[p - 1].w < 1e30f) s += C_IL[p];   // NaN compare -> false
        idcg = (s > 0.0f) ? (1.0f / s) : 0.0f;
    }

    // --- pair loop: orientation-free identity (exact for both directions):
    //     bce = ln2*lg2(Gi+Gj) - hi + dh*Ej/(Ei+Ej),  dh = hi-hj
    //     w = rel[ci-cj+51] + 0.25|di-dj|;  mask |labi-labj|>0 (NaN-safe) ---
    const float*  relb = s_rel + ((capped + 51) << 5) + lane;  // - (cj<<5) per pair
    const float4* pA   = sA  + tid + 1 + (h << 7);
    const float*  pB   = sBp + tid + 1 + (h << 7);

    auto body = [&](const float4 A, const float Bp) -> float {
        const float t2  = __fdividef(A.y, Ei + A.y);
        const float lg  = __log2f(Gi + A.x);
        const float dh  = hi - A.z;
        const float bce = fmaf(dh, t2, fmaf(lg, LN2F, nhi));
        const float dl  = labi - A.w;                 // NaN if either invalid
        const int   cj  = (int)(__float_as_uint(Bp) & 0xFFu);
        float w = relb[-(cj << 5)] + fabsf(qdi - Bp); // bank==lane, conflict-free
        w = (fabsf(dl) > 0.0f) ? w : 0.0f;
        return bce * w;
    };

    float acc0 = 0.0f, acc1 = 0.0f, acc2 = 0.0f, acc3 = 0.0f;
    int oo = 0;
    for (; oo + 4 <= 124; oo += 4) {      // 4-wide staged: 8 LDS in flight, 4 chains
        const float4 A0 = pA[oo],     A1 = pA[oo + 1];
        const float4 A2 = pA[oo + 2], A3 = pA[oo + 3];
        const float  B0 = pB[oo],     B1 = pB[oo + 1];
        const float  B2 = pB[oo + 2], B3 = pB[oo + 3];
        acc0 += body(A0, B0);
        acc1 += body(A1, B1);
        acc2 += body(A2, B2);
        acc3 += body(A3, B3);
    }
    for (; oo < 127; ++oo)                // offsets 124..126
        acc0 += body(pA[oo], pB[oo]);
    {   // final offset (128 or 256); offset 256 double-covered -> gate tid<256
        const bool gate = (h == 0) | (tid < 256);
        const float v = body(pA[127], pB[127]);
        acc1 += gate ? v : 0.0f;
    }
    float acc = (acc0 + acc1) + (acc2 + acc3);

    // --- deterministic block reduce + fused final reduce ---
    #pragma unroll
    for (int o = 16; o; o >>= 1) acc += __shfl_down_sync(0xffffffffu, acc, o);
    if (lane == 0) s_red[tid >> 5] = acc;
    __syncthreads();
    if (tid < 16) {
        float v = s_red[tid];
        #pragma unroll
        for (int o = 8; o; o >>= 1) v += __shfl_down_sync(0xffffu, v, o);
        if (tid == 0) {
            g_partial[blockIdx.x] = v * idcg * (1.0f / (float)BATCH);
            __threadfence();
            unsigned int old = atomicInc(&g_count, NBLK - 1);  // wraps -> replay-safe
            s_last = (old == NBLK - 1);
        }
    }
    __syncthreads();

    if (s_last) {
        __threadfence();
        if (tid < NBLK) {
            float v = ((volatile float*)g_partial)[tid];
            #pragma unroll
            for (int o = 16; o; o >>= 1) v += __shfl_down_sync(0xffffffffu, v, o);
            if (lane == 0) s_red[tid >> 5] = v;
        }
        __syncthreads();
        if (tid == 0) {
            float tot = 0.0f;
            #pragma unroll
            for (int w2 = 0; w2 < NBLK / 32; ++w2) tot += s_red[w2];
            out[0] = tot;
        }
    }
}

extern "C" void kernel_launch(void* const* d_in, const int* in_sizes, int n_in,
                              void* d_out, int out_size) {
    const float* logits = (const float*)d_in[0];
    const float* labels = (const float*)d_in[1];
    float* out = (float*)d_out;
    (void)in_sizes; (void)n_in; (void)out_size;

    rank_loss_main<<<NBLK, THREADS>>>(logits, labels, out);
}